// round 16
// baseline (speedup 1.0000x reference)
#include <cuda_runtime.h>
#include <cuda_fp16.h>

#define NN 256
#define THREADS 256
#define ITERS 20
#define TOL 4e-4f
#define OMEGA_M1 0.3f   // SOR over-relaxation exponent (omega - 1)

// smem layout (bytes), per CTA 75272 (x2 = 150544 <= 228KB/SM):
//   [0,     50688)  Ksm: rows 160..255 (96 rows x 33 uint4, 264 halves/row)
//   [50688, 55296)  redc: 4 x 288 half2 (col partials)
//   [55296, 72704)  wbuf: 8 warps x 16 slots x 34 words (packed half2 row partials)
//   [50688, 71808)  (epilogue) stg: 40 rows x 33 uint4 staging — overlaps redc+wbuf
//   [72704, 73216)  Bth2: 128 half2
//   [73216, 74240)  Bf: 256 float
//   [74240, 75264)  Af: 256 float
//   [75264, 75272)  flags[2]
#define SM_BYTES 75272

__device__ __forceinline__ float rowdot8(uint4 kvr, const __half2* b2) {
    const __half2* kh = (const __half2*)&kvr;
    __half2 p = __hmul2(kh[0], b2[0]);
    p = __hfma2(kh[1], b2[1], p);
    p = __hfma2(kh[2], b2[2], p);
    p = __hfma2(kh[3], b2[3], p);
    float2 f = __half22float2(p);
    return f.x + f.y;
}

// streaming store: evict-first in L2 (output is write-once, never re-read)
__device__ __forceinline__ void stg_cs_v4(float* p, float4 v) {
    asm volatile("st.global.cs.v4.f32 [%0], {%1, %2, %3, %4};"
                 :: "l"(p), "f"(v.x), "f"(v.y), "f"(v.z), "f"(v.w) : "memory");
}

__global__ __launch_bounds__(THREADS, 2)
void sinkhorn_kernel(const float* __restrict__ x, float* __restrict__ out) {
    extern __shared__ char sm[];
    __half*   Ksm   = (__half*)sm;
    __half2*  Ksm2  = (__half2*)sm;
    uint4*    Ksm4  = (uint4*)sm;
    __half2*  redc  = (__half2*)(sm + 50688);
    unsigned* wbuf  = (unsigned*)(sm + 55296);
    uint4*    stg4  = (uint4*)(sm + 50688);    // epilogue staging overlaps redc+wbuf
    __half2*  stg2  = (__half2*)(sm + 50688);
    __half2*  Bth2  = (__half2*)(sm + 72704);
    float*    Bf    = (float*)(sm + 73216);
    float*    Af    = (float*)(sm + 74240);
    volatile int* flags = (volatile int*)(sm + 75264);

    const int t = threadIdx.x;
    const int l = t & 31;          // lane: owns halves 8l..8l+7 of its rows
    const int w = t >> 5;          // warp: reg rows 20w..20w+19, smem rows 160+12w..+11
    const size_t base = (size_t)blockIdx.x * (NN * NN);
    const float* xm = x + base;
    float* om = out + base;
    unsigned* wbufw = wbuf + w * 544;   // 16 slots x 34 words, warp-private

    uint4 kv[20];                  // register K: rows 20w..20w+19, fp16

    // reader mapping for the packed row-partial staging (local rows 0..31)
    int rs, rc_, rg;
    if (l < 12)      { rs = l;                  rc_ = 0;            rg = 20 * w + l; }
    else if (l < 20) { rs = 12 + ((l - 12) >> 1); rc_ = (l - 12) & 1; rg = 20 * w + l; }
    else             { rs = l - 20;             rc_ = 1;            rg = 160 + 12 * w + (l - 20); }

    // L2 prefetch target: the matrix a wave-2 CTA will read (296 CTAs ahead)
    const char* pfp = (const char*)(x + ((size_t)blockIdx.x + 296) * (NN * NN)) + t * 128;
    const bool do_pf = (blockIdx.x + 296) < (unsigned)gridDim.x;

    // ---------------- setup: reg rows 0..159 direct gmem->reg ----------------
    #pragma unroll
    for (int r = 0; r < 20; r++) {
        const float* rp = xm + (20 * w + r) * NN + 8 * l;
        float4 v0 = *(const float4*)rp;
        float4 v1 = *(const float4*)(rp + 4);
        __half2 h0 = __floats2half2_rn(__expf(v0.x), __expf(v0.y));
        __half2 h1 = __floats2half2_rn(__expf(v0.z), __expf(v0.w));
        __half2 h2 = __floats2half2_rn(__expf(v1.x), __expf(v1.y));
        __half2 h3 = __floats2half2_rn(__expf(v1.z), __expf(v1.w));
        kv[r].x = *(unsigned*)&h0;
        kv[r].y = *(unsigned*)&h1;
        kv[r].z = *(unsigned*)&h2;
        kv[r].w = *(unsigned*)&h3;
    }
    // ---------------- setup: smem rows 160..255, coalesced ----------------
    #pragma unroll
    for (int k = 0; k < 24; k++) {
        int idx = (k * THREADS + t) * 4;
        float4 v = *(const float4*)(xm + 160 * NN + idx);
        int i = idx >> 8, j = idx & 255;
        *(__half2*)(Ksm + i * 264 + j)     = __floats2half2_rn(__expf(v.x), __expf(v.y));
        *(__half2*)(Ksm + i * 264 + j + 2) = __floats2half2_rn(__expf(v.z), __expf(v.w));
    }
    float   myAf = 1.0f;                               // A of local row l (lane-resident)
    __half2 one2 = __floats2half2_rn(1.0f, 1.0f);
    unsigned myA2u = *(unsigned*)&one2;
    if (t < NN) Af[t] = 1.0f;
    if (t == 0) { flags[0] = 0; flags[1] = 0; }
    __syncthreads();

    // ---------------- main loop ----------------
    for (int it = 0; it < ITERS; it++) {
        // ===== column pass: 32 rows/thread (20 reg + 12 smem), A via SHFL =====
        __half2 z = __floats2half2_rn(0.f, 0.f);
        __half2 acc0 = z, acc1 = z, acc2 = z, acc3 = z;
        #pragma unroll
        for (int r = 0; r < 20; r++) {
            unsigned au = __shfl_sync(0xffffffffu, myA2u, r);
            __half2 a2 = *(__half2*)&au;
            const __half2* kh = (const __half2*)&kv[r];
            acc0 = __hfma2(kh[0], a2, acc0);
            acc1 = __hfma2(kh[1], a2, acc1);
            acc2 = __hfma2(kh[2], a2, acc2);
            acc3 = __hfma2(kh[3], a2, acc3);
        }
        #pragma unroll
        for (int r = 0; r < 12; r++) {
            uint4 ks = Ksm4[(12 * w + r) * 33 + l];     // contiguous: conflict-free
            unsigned au = __shfl_sync(0xffffffffu, myA2u, 20 + r);
            __half2 a2 = *(__half2*)&au;
            const __half2* kh = (const __half2*)&ks;
            acc0 = __hfma2(kh[0], a2, acc0);
            acc1 = __hfma2(kh[1], a2, acc1);
            acc2 = __hfma2(kh[2], a2, acc2);
            acc3 = __hfma2(kh[3], a2, acc3);
        }
        redc[0 * 288 + l * 9 + w] = acc0;   // bank (9l+w)%32: conflict-free
        redc[1 * 288 + l * 9 + w] = acc1;
        redc[2 * 288 + l * 9 + w] = acc2;
        redc[3 * 288 + l * 9 + w] = acc3;
        if (it < 8 && do_pf) {              // warm L2 with wave-2 inputs (DRAM-idle window)
            asm volatile("prefetch.global.L2 [%0];" :: "l"(pfp + (size_t)it * 32768));
        }
        __syncthreads();                                // barrier (1)
        if (it > 0 && flags[(it - 1) & 1] == 0) break;  // uniform post-barrier read
        if (t < 128) {                                  // fp32 reduce over 8 slices + rcp
            int e = t >> 5, u2 = t & 31;
            const __half2* p = redc + e * 288 + u2 * 9; // conflict-free
            float c0a = 0.f, c0b = 0.f, c1a = 0.f, c1b = 0.f;
            #pragma unroll
            for (int k = 0; k < 8; k += 2) {
                float2 f0 = __half22float2(p[k]);
                float2 f1 = __half22float2(p[k + 1]);
                c0a += f0.x; c1a += f0.y;
                c0b += f1.x; c1b += f1.y;
            }
            float b0 = 1.0f / (c0a + c0b), b1 = 1.0f / (c1a + c1b);
            int j2 = 4 * u2 + e;
            Bth2[j2] = __floats2half2_rn(b0, b1);
            Bf[2 * j2]     = b0;
            Bf[2 * j2 + 1] = b1;
        }
        __syncthreads();                                // barrier (2)

        // ===== row pass: warp-local, partials packed fp16 =====
        uint4 bt = *(const uint4*)(Bth2 + 4 * l);       // LDS.128, conflict-free
        const __half2* b2 = (const __half2*)&bt;
        #pragma unroll
        for (int r = 0; r < 12; r++) {                  // pair (reg row r, smem row r)
            float pR = rowdot8(kv[r], b2);
            uint4 ks = Ksm4[(12 * w + r) * 33 + l];
            float pS = rowdot8(ks, b2);
            __half2 hp = __floats2half2_rn(pR, pS);
            wbufw[r * 34 + l] = *(unsigned*)&hp;        // bank (2r+l)%32: conflict-free
        }
        #pragma unroll
        for (int q = 0; q < 4; q++) {                   // pair (reg 12+2q, reg 13+2q)
            float pA = rowdot8(kv[12 + 2 * q], b2);
            float pB = rowdot8(kv[13 + 2 * q], b2);
            __half2 hp = __floats2half2_rn(pA, pB);
            wbufw[(12 + q) * 34 + l] = *(unsigned*)&hp;
        }
        __syncwarp();
        {   // lane l reduces its local row; SOR-accelerated A update
            const uint2* pp = (const uint2*)(wbufw + rs * 34);  // stride 34: conflict-free LDS.64
            float sx0 = 0, sx1 = 0, sy0 = 0, sy1 = 0;
            #pragma unroll
            for (int k = 0; k < 16; k++) {
                uint2 v = pp[k];
                float2 fa = __half22float2(*(__half2*)&v.x);
                float2 fb = __half22float2(*(__half2*)&v.y);
                sx0 += fa.x; sy0 += fa.y;
                sx1 += fb.x; sy1 += fb.y;
            }
            float denom = rc_ ? (sy0 + sy1) : (sx0 + sx1);
            float a_gs = 1.0f / denom;                           // Gauss-Seidel value
            if (fabsf(a_gs - myAf) > TOL * myAf) flags[it & 1] = 1;  // benign race
            // SOR: a = a_gs * (a_gs/a_prev)^(omega-1); fixed point unchanged
            float a = a_gs * __powf(a_gs / myAf, OMEGA_M1);
            myAf = a;
            __half2 ah = __floats2half2_rn(a, a);
            myA2u = *(unsigned*)&ah;
            Af[rg] = a;
        }
        if (t == 0) flags[(it + 1) & 1] = 0;            // reset other slot (barrier-separated)
        __syncwarp();
    }
    __syncthreads();                                    // A/B visible; loop smem reads done

    // ---------------- epilogue (streaming .cs stores) ----------------
    const int cc = t & 63;                              // my float4 column group
    const float4 bq = *(const float4*)(Bf + 4 * cc);

    // smem half (rows 160..255): direct, coalesced
    #pragma unroll
    for (int k = 0; k < 24; k++) {
        int rc = k * 4 + (t >> 6);                      // 0..95
        uint2 kk = *(const uint2*)(Ksm2 + rc * 132 + 2 * cc);
        float ai = Af[160 + rc];
        float2 f0 = __half22float2(*(__half2*)&kk.x);
        float2 f1 = __half22float2(*(__half2*)&kk.y);
        float4 o;
        o.x = f0.x * ai * bq.x;
        o.y = f0.y * ai * bq.y;
        o.z = f1.x * ai * bq.z;
        o.w = f1.y * ai * bq.w;
        stg_cs_v4(om + (160 + rc) * NN + 4 * cc, o);
    }
    // reg half (rows 0..159): 4 chunks of 40 rows via staging transpose
    #pragma unroll
    for (int c = 0; c < 4; c++) {
        __syncthreads();
        if ((w >> 1) == c) {                            // warps 2c,2c+1 stage their 20 rows
            #pragma unroll
            for (int r = 0; r < 20; r++)
                stg4[(20 * (w & 1) + r) * 33 + l] = kv[r];   // conflict-free
        }
        __syncthreads();
        #pragma unroll
        for (int k = 0; k < 10; k++) {
            int rc = k * 4 + (t >> 6);                  // 0..39
            uint2 kk = *(const uint2*)(stg2 + rc * 132 + 2 * cc);
            float ai = Af[40 * c + rc];
            float2 f0 = __half22float2(*(__half2*)&kk.x);
            float2 f1 = __half22float2(*(__half2*)&kk.y);
            float4 o;
            o.x = f0.x * ai * bq.x;
            o.y = f0.y * ai * bq.y;
            o.z = f1.x * ai * bq.z;
            o.w = f1.y * ai * bq.w;
            stg_cs_v4(om + (40 * c + rc) * NN + 4 * cc, o);
        }
    }
}

extern "C" void kernel_launch(void* const* d_in, const int* in_sizes, int n_in,
                              void* d_out, int out_size) {
    const float* x = (const float*)d_in[0];
    float* out = (float*)d_out;
    int n_mat = in_sizes[0] / (NN * NN);      // 512
    cudaFuncSetAttribute(sinkhorn_kernel,
                         cudaFuncAttributeMaxDynamicSharedMemorySize, SM_BYTES);
    sinkhorn_kernel<<<n_mat, THREADS, SM_BYTES>>>(x, out);
}

// round 17
// speedup vs baseline: 1.2388x; 1.2388x over previous
#include <cuda_runtime.h>
#include <cuda_fp16.h>

#define NN 256
#define THREADS 256
#define ITERS 20
#define TOL 6e-4f

// smem layout (bytes), per CTA 75272 (x2 = 150544 <= 228KB/SM):
//   [0,     50688)  Ksm: rows 160..255 (96 rows x 33 uint4, 264 halves/row)
//   [50688, 55296)  redc: 4 x 288 half2 (col partials)
//   [55296, 72704)  wbuf: 8 warps x 16 slots x 34 words (packed half2 row partials)
//   [50688, 71808)  (epilogue) stg: 40 rows x 33 uint4 staging — overlaps redc+wbuf
//   [72704, 73216)  Bth2: 128 half2
//   [73216, 74240)  Bf: 256 float
//   [74240, 75264)  Af: 256 float
//   [75264, 75272)  flags[2]
#define SM_BYTES 75272

__device__ __forceinline__ float rowdot8(uint4 kvr, const __half2* b2) {
    const __half2* kh = (const __half2*)&kvr;
    __half2 p = __hmul2(kh[0], b2[0]);
    p = __hfma2(kh[1], b2[1], p);
    p = __hfma2(kh[2], b2[2], p);
    p = __hfma2(kh[3], b2[3], p);
    float2 f = __half22float2(p);
    return f.x + f.y;
}

// streaming store: evict-first in L2 (output is write-once, never re-read)
__device__ __forceinline__ void stg_cs_v4(float* p, float4 v) {
    asm volatile("st.global.cs.v4.f32 [%0], {%1, %2, %3, %4};"
                 :: "l"(p), "f"(v.x), "f"(v.y), "f"(v.z), "f"(v.w) : "memory");
}

__global__ __launch_bounds__(THREADS, 2)
void sinkhorn_kernel(const float* __restrict__ x, float* __restrict__ out) {
    extern __shared__ char sm[];
    __half*   Ksm   = (__half*)sm;
    __half2*  Ksm2  = (__half2*)sm;
    uint4*    Ksm4  = (uint4*)sm;
    __half2*  redc  = (__half2*)(sm + 50688);
    unsigned* wbuf  = (unsigned*)(sm + 55296);
    uint4*    stg4  = (uint4*)(sm + 50688);    // epilogue staging overlaps redc+wbuf
    __half2*  stg2  = (__half2*)(sm + 50688);
    __half2*  Bth2  = (__half2*)(sm + 72704);
    float*    Bf    = (float*)(sm + 73216);
    float*    Af    = (float*)(sm + 74240);
    volatile int* flags = (volatile int*)(sm + 75264);

    const int t = threadIdx.x;
    const int l = t & 31;          // lane: owns halves 8l..8l+7 of its rows
    const int w = t >> 5;          // warp: reg rows 20w..20w+19, smem rows 160+12w..+11
    const size_t base = (size_t)blockIdx.x * (NN * NN);
    const float* xm = x + base;
    float* om = out + base;
    unsigned* wbufw = wbuf + w * 544;   // 16 slots x 34 words, warp-private

    uint4 kv[20];                  // register K: rows 20w..20w+19, fp16

    // reader mapping for the packed row-partial staging (local rows 0..31)
    int rs, rc_, rg;
    if (l < 12)      { rs = l;                  rc_ = 0;            rg = 20 * w + l; }
    else if (l < 20) { rs = 12 + ((l - 12) >> 1); rc_ = (l - 12) & 1; rg = 20 * w + l; }
    else             { rs = l - 20;             rc_ = 1;            rg = 160 + 12 * w + (l - 20); }

    // L2 prefetch target: the matrix a wave-2 CTA will read (296 CTAs ahead)
    const char* pfp = (const char*)(x + ((size_t)blockIdx.x + 296) * (NN * NN)) + t * 128;
    const bool do_pf = (blockIdx.x + 296) < (unsigned)gridDim.x;

    // ---------------- setup: reg rows 0..159 direct gmem->reg ----------------
    #pragma unroll
    for (int r = 0; r < 20; r++) {
        const float* rp = xm + (20 * w + r) * NN + 8 * l;
        float4 v0 = *(const float4*)rp;
        float4 v1 = *(const float4*)(rp + 4);
        __half2 h0 = __floats2half2_rn(__expf(v0.x), __expf(v0.y));
        __half2 h1 = __floats2half2_rn(__expf(v0.z), __expf(v0.w));
        __half2 h2 = __floats2half2_rn(__expf(v1.x), __expf(v1.y));
        __half2 h3 = __floats2half2_rn(__expf(v1.z), __expf(v1.w));
        kv[r].x = *(unsigned*)&h0;
        kv[r].y = *(unsigned*)&h1;
        kv[r].z = *(unsigned*)&h2;
        kv[r].w = *(unsigned*)&h3;
    }
    // ---------------- setup: smem rows 160..255, coalesced ----------------
    #pragma unroll
    for (int k = 0; k < 24; k++) {
        int idx = (k * THREADS + t) * 4;
        float4 v = *(const float4*)(xm + 160 * NN + idx);
        int i = idx >> 8, j = idx & 255;
        *(__half2*)(Ksm + i * 264 + j)     = __floats2half2_rn(__expf(v.x), __expf(v.y));
        *(__half2*)(Ksm + i * 264 + j + 2) = __floats2half2_rn(__expf(v.z), __expf(v.w));
    }
    float   myAf = 1.0f;                               // A of local row l (lane-resident)
    __half2 one2 = __floats2half2_rn(1.0f, 1.0f);
    unsigned myA2u = *(unsigned*)&one2;
    if (t == 0) { flags[0] = 0; flags[1] = 0; }
    __syncthreads();

    // ---------------- warm start: A0 = 1/rowsum(K) (row sweep with B = 1) ----------------
    {
        __half2 ones[4] = {one2, one2, one2, one2};
        #pragma unroll
        for (int r = 0; r < 12; r++) {                  // pair (reg row r, smem row r)
            float pR = rowdot8(kv[r], ones);
            uint4 ks = Ksm4[(12 * w + r) * 33 + l];
            float pS = rowdot8(ks, ones);
            __half2 hp = __floats2half2_rn(pR, pS);
            wbufw[r * 34 + l] = *(unsigned*)&hp;
        }
        #pragma unroll
        for (int q = 0; q < 4; q++) {                   // pair (reg 12+2q, reg 13+2q)
            float pA = rowdot8(kv[12 + 2 * q], ones);
            float pB = rowdot8(kv[13 + 2 * q], ones);
            __half2 hp = __floats2half2_rn(pA, pB);
            wbufw[(12 + q) * 34 + l] = *(unsigned*)&hp;
        }
        __syncwarp();
        {
            const uint2* pp = (const uint2*)(wbufw + rs * 34);
            float sx0 = 0, sx1 = 0, sy0 = 0, sy1 = 0;
            #pragma unroll
            for (int k = 0; k < 16; k++) {
                uint2 v = pp[k];
                float2 fa = __half22float2(*(__half2*)&v.x);
                float2 fb = __half22float2(*(__half2*)&v.y);
                sx0 += fa.x; sy0 += fa.y;
                sx1 += fb.x; sy1 += fb.y;
            }
            float denom = rc_ ? (sy0 + sy1) : (sx0 + sx1);
            float a = 1.0f / denom;
            myAf = a;
            __half2 ah = __floats2half2_rn(a, a);
            myA2u = *(unsigned*)&ah;
            Af[rg] = a;
        }
        __syncwarp();
    }

    // ---------------- main loop ----------------
    for (int it = 0; it < ITERS; it++) {
        // ===== column pass: 32 rows/thread (20 reg + 12 smem), A via SHFL =====
        __half2 z = __floats2half2_rn(0.f, 0.f);
        __half2 acc0 = z, acc1 = z, acc2 = z, acc3 = z;
        #pragma unroll
        for (int r = 0; r < 20; r++) {
            unsigned au = __shfl_sync(0xffffffffu, myA2u, r);
            __half2 a2 = *(__half2*)&au;
            const __half2* kh = (const __half2*)&kv[r];
            acc0 = __hfma2(kh[0], a2, acc0);
            acc1 = __hfma2(kh[1], a2, acc1);
            acc2 = __hfma2(kh[2], a2, acc2);
            acc3 = __hfma2(kh[3], a2, acc3);
        }
        #pragma unroll
        for (int r = 0; r < 12; r++) {
            uint4 ks = Ksm4[(12 * w + r) * 33 + l];     // contiguous: conflict-free
            unsigned au = __shfl_sync(0xffffffffu, myA2u, 20 + r);
            __half2 a2 = *(__half2*)&au;
            const __half2* kh = (const __half2*)&ks;
            acc0 = __hfma2(kh[0], a2, acc0);
            acc1 = __hfma2(kh[1], a2, acc1);
            acc2 = __hfma2(kh[2], a2, acc2);
            acc3 = __hfma2(kh[3], a2, acc3);
        }
        redc[0 * 288 + l * 9 + w] = acc0;   // bank (9l+w)%32: conflict-free
        redc[1 * 288 + l * 9 + w] = acc1;
        redc[2 * 288 + l * 9 + w] = acc2;
        redc[3 * 288 + l * 9 + w] = acc3;
        if (it < 8 && do_pf) {              // warm L2 with wave-2 inputs (DRAM-idle window)
            asm volatile("prefetch.global.L2 [%0];" :: "l"(pfp + (size_t)it * 32768));
        }
        __syncthreads();                                // barrier (1)
        if (it > 0 && flags[(it - 1) & 1] == 0) break;  // uniform post-barrier read
        if (t < 128) {                                  // fp32 reduce over 8 slices + rcp
            int e = t >> 5, u2 = t & 31;
            const __half2* p = redc + e * 288 + u2 * 9; // conflict-free
            float c0a = 0.f, c0b = 0.f, c1a = 0.f, c1b = 0.f;
            #pragma unroll
            for (int k = 0; k < 8; k += 2) {
                float2 f0 = __half22float2(p[k]);
                float2 f1 = __half22float2(p[k + 1]);
                c0a += f0.x; c1a += f0.y;
                c0b += f1.x; c1b += f1.y;
            }
            float b0 = 1.0f / (c0a + c0b), b1 = 1.0f / (c1a + c1b);
            int j2 = 4 * u2 + e;
            Bth2[j2] = __floats2half2_rn(b0, b1);
            Bf[2 * j2]     = b0;
            Bf[2 * j2 + 1] = b1;
        }
        __syncthreads();                                // barrier (2)

        // ===== row pass: warp-local, partials packed fp16 =====
        uint4 bt = *(const uint4*)(Bth2 + 4 * l);       // LDS.128, conflict-free
        const __half2* b2 = (const __half2*)&bt;
        #pragma unroll
        for (int r = 0; r < 12; r++) {                  // pair (reg row r, smem row r)
            float pR = rowdot8(kv[r], b2);
            uint4 ks = Ksm4[(12 * w + r) * 33 + l];
            float pS = rowdot8(ks, b2);
            __half2 hp = __floats2half2_rn(pR, pS);
            wbufw[r * 34 + l] = *(unsigned*)&hp;        // bank (2r+l)%32: conflict-free
        }
        #pragma unroll
        for (int q = 0; q < 4; q++) {                   // pair (reg 12+2q, reg 13+2q)
            float pA = rowdot8(kv[12 + 2 * q], b2);
            float pB = rowdot8(kv[13 + 2 * q], b2);
            __half2 hp = __floats2half2_rn(pA, pB);
            wbufw[(12 + q) * 34 + l] = *(unsigned*)&hp;
        }
        __syncwarp();
        {   // lane l reduces its local row (component rc_ of slot rs)
            const uint2* pp = (const uint2*)(wbufw + rs * 34);  // stride 34: conflict-free LDS.64
            float sx0 = 0, sx1 = 0, sy0 = 0, sy1 = 0;
            #pragma unroll
            for (int k = 0; k < 16; k++) {
                uint2 v = pp[k];
                float2 fa = __half22float2(*(__half2*)&v.x);
                float2 fb = __half22float2(*(__half2*)&v.y);
                sx0 += fa.x; sy0 += fa.y;
                sx1 += fb.x; sy1 += fb.y;
            }
            float denom = rc_ ? (sy0 + sy1) : (sx0 + sx1);
            float a = 1.0f / denom;
            if (fabsf(a - myAf) > TOL * myAf) flags[it & 1] = 1;   // benign race
            myAf = a;
            __half2 ah = __floats2half2_rn(a, a);
            myA2u = *(unsigned*)&ah;
            Af[rg] = a;
        }
        if (t == 0) flags[(it + 1) & 1] = 0;            // reset other slot (barrier-separated)
        __syncwarp();
    }
    __syncthreads();                                    // A/B visible; loop smem reads done

    // ---------------- epilogue (streaming .cs stores) ----------------
    const int cc = t & 63;                              // my float4 column group
    const float4 bq = *(const float4*)(Bf + 4 * cc);

    // smem half (rows 160..255): direct, coalesced
    #pragma unroll
    for (int k = 0; k < 24; k++) {
        int rc = k * 4 + (t >> 6);                      // 0..95
        uint2 kk = *(const uint2*)(Ksm2 + rc * 132 + 2 * cc);
        float ai = Af[160 + rc];
        float2 f0 = __half22float2(*(__half2*)&kk.x);
        float2 f1 = __half22float2(*(__half2*)&kk.y);
        float4 o;
        o.x = f0.x * ai * bq.x;
        o.y = f0.y * ai * bq.y;
        o.z = f1.x * ai * bq.z;
        o.w = f1.y * ai * bq.w;
        stg_cs_v4(om + (160 + rc) * NN + 4 * cc, o);
    }
    // reg half (rows 0..159): 4 chunks of 40 rows via staging transpose
    #pragma unroll
    for (int c = 0; c < 4; c++) {
        __syncthreads();
        if ((w >> 1) == c) {                            // warps 2c,2c+1 stage their 20 rows
            #pragma unroll
            for (int r = 0; r < 20; r++)
                stg4[(20 * (w & 1) + r) * 33 + l] = kv[r];   // conflict-free
        }
        __syncthreads();
        #pragma unroll
        for (int k = 0; k < 10; k++) {
            int rc = k * 4 + (t >> 6);                  // 0..39
            uint2 kk = *(const uint2*)(stg2 + rc * 132 + 2 * cc);
            float ai = Af[40 * c + rc];
            float2 f0 = __half22float2(*(__half2*)&kk.x);
            float2 f1 = __half22float2(*(__half2*)&kk.y);
            float4 o;
            o.x = f0.x * ai * bq.x;
            o.y = f0.y * ai * bq.y;
            o.z = f1.x * ai * bq.z;
            o.w = f1.y * ai * bq.w;
            stg_cs_v4(om + (40 * c + rc) * NN + 4 * cc, o);
        }
    }
}

extern "C" void kernel_launch(void* const* d_in, const int* in_sizes, int n_in,
                              void* d_out, int out_size) {
    const float* x = (const float*)d_in[0];
    float* out = (float*)d_out;
    int n_mat = in_sizes[0] / (NN * NN);      // 512
    cudaFuncSetAttribute(sinkhorn_kernel,
                         cudaFuncAttributeMaxDynamicSharedMemorySize, SM_BYTES);
    sinkhorn_kernel<<<n_mat, THREADS, SM_BYTES>>>(x, out);
}